// round 16
// baseline (speedup 1.0000x reference)
#include <cuda_runtime.h>

// Spacial IRNN: 4 directional relu-scans over [B,C,H,W] = [4,64,256,256] fp32.
// out[dir][b][c][h][w], dir: 0=up, 1=right, 2=down, 3=left.
// h_0 = x_edge (raw), h_t = relu(w_c * h_{t-1} + b_c + x_t).
//
// Key identity: maps h -> max(a*h + b, m) are closed under composition
// (a2>=0):  a = a2*a1, b = a2*b1 + b2, m = max(a2*m1 + b2, m2).
// Element map: h -> max(w*h + (b+x), 0); row edge: (0, x_edge, -1e30).
// So each ROW x DIRECTION is one warp: coalesced 32-wide loads, 5-level
// Kogge-Stone composition via shfl (no smem, no barriers, no LSU overhead),
// apply to running carry, coalesced streaming stores.
//
// Grid: blocks 0..511 = vertical (R9-proven scalar path, one direction per
// block); blocks 512+ = horizontal, 8 warps/block, warp gw = (row, dir).

#define HH 256
#define WW 256
#define BB 4
#define CC 64

constexpr int HW = HH * WW;
constexpr long long DIRSZ = (long long)BB * CC * HH * WW;  // 16,777,216

constexpr int TPB    = 256;
constexpr int VGRID  = 512;                       // vertical blocks
constexpr int NROWS  = BB * CC * HH;              // 65,536
constexpr int HGRID  = (NROWS * 2) / 8;           // 16,384 (8 warps/block)

__global__ void __launch_bounds__(TPB)
irnn_fused_kernel(const float* __restrict__ x,
                  const float* __restrict__ w_up,    const float* __restrict__ b_up,
                  const float* __restrict__ w_right, const float* __restrict__ b_right,
                  const float* __restrict__ w_down,  const float* __restrict__ b_down,
                  const float* __restrict__ w_left,  const float* __restrict__ b_left,
                  float* __restrict__ out)
{
    const int bid = blockIdx.x;
    const int tid = threadIdx.x;

    if (bid < VGRID) {
        // ---------------- vertical: one direction, one thread per column ----
        const int isUp = bid & 1;            // 0 = down, 1 = up
        const int unit = bid >> 1;           // 0 .. 255

        const int id = unit * TPB + tid;     // 0 .. B*C*W-1
        const int w  = id & (WW - 1);
        const int bc = id >> 8;
        const int c  = bc & (CC - 1);

        const float* xp = x + (size_t)bc * HW + w;

        if (!isUp) {
            float* od = out + 2 * DIRSZ + (size_t)bc * HW + w;   // down
            const float wd = w_down[c], bd = b_down[c];
            float s = xp[0];
            __stcs(&od[0], s);
#pragma unroll 8
            for (int h = 1; h < HH; ++h) {
                float xv = xp[h * WW];
                s = fmaxf(fmaf(wd, s, bd + xv), 0.0f);
                __stcs(&od[h * WW], s);
            }
        } else {
            float* ou = out + 0 * DIRSZ + (size_t)bc * HW + w;   // up
            const float wu = w_up[c], bu = b_up[c];
            float s = xp[(HH - 1) * WW];
            __stcs(&ou[(HH - 1) * WW], s);
#pragma unroll 8
            for (int h = HH - 2; h >= 0; --h) {
                float xv = xp[h * WW];
                s = fmaxf(fmaf(wu, s, bu + xv), 0.0f);
                __stcs(&ou[h * WW], s);
            }
        }
    } else {
        // --------------- horizontal: one warp per (row, direction) ----------
        const int gw   = (bid - VGRID) * 8 + (tid >> 5);   // 0 .. 131071
        const int lane = tid & 31;
        const int row    = gw >> 1;
        const bool isLeft = gw & 1;                        // uniform per warp
        const int c = (row >> 8) & (CC - 1);

        const float* xr = x + (size_t)row * WW;
        float* orow = out + (isLeft ? 3 : 1) * DIRSZ + (size_t)row * WW;

        const float wsc = isLeft ? w_left[c] : w_right[c];
        const float bsc = isLeft ? b_left[c] : b_right[c];

        float s = 0.0f;
#pragma unroll
        for (int ci = 0; ci < 8; ++ci) {
            const int ch  = isLeft ? (7 - ci) : ci;
            const int col = ch * 32 + lane;
            const float xv = xr[col];                       // coalesced

            // per-element map triple (a, b, m): h -> max(a*h + b, m)
            float a = wsc, b = bsc + xv, m = 0.0f;
            const bool edge = (ci == 0) && (lane == (isLeft ? 31 : 0));
            if (edge) { a = 0.0f; b = xv; m = -1e30f; }     // raw boundary

            // Kogge-Stone inclusive composition along the scan direction.
            // current triple is the OUTER map, shfl'd triple the INNER map.
            if (!isLeft) {
#pragma unroll
                for (int d = 1; d < 32; d <<= 1) {
                    float a1 = __shfl_up_sync(0xffffffffu, a, d);
                    float b1 = __shfl_up_sync(0xffffffffu, b, d);
                    float m1 = __shfl_up_sync(0xffffffffu, m, d);
                    if (lane >= d) {
                        float nm = fmaxf(fmaf(a, m1, b), m);
                        float nb = fmaf(a, b1, b);
                        a = a * a1; b = nb; m = nm;
                    }
                }
            } else {
#pragma unroll
                for (int d = 1; d < 32; d <<= 1) {
                    float a1 = __shfl_down_sync(0xffffffffu, a, d);
                    float b1 = __shfl_down_sync(0xffffffffu, b, d);
                    float m1 = __shfl_down_sync(0xffffffffu, m, d);
                    if (lane + d < 32) {
                        float nm = fmaxf(fmaf(a, m1, b), m);
                        float nb = fmaf(a, b1, b);
                        a = a * a1; b = nb; m = nm;
                    }
                }
            }

            // apply composed map to incoming state; store; update carry
            float o = fmaxf(fmaf(a, s, b), m);
            __stcs(&orow[col], o);
            s = __shfl_sync(0xffffffffu, o, isLeft ? 0 : 31);
        }
    }
}

extern "C" void kernel_launch(void* const* d_in, const int* in_sizes, int n_in,
                              void* d_out, int out_size)
{
    const float* x       = (const float*)d_in[0];
    const float* w_up    = (const float*)d_in[1];
    const float* w_right = (const float*)d_in[2];
    const float* w_down  = (const float*)d_in[3];
    const float* w_left  = (const float*)d_in[4];
    const float* b_up    = (const float*)d_in[5];
    const float* b_right = (const float*)d_in[6];
    const float* b_down  = (const float*)d_in[7];
    const float* b_left  = (const float*)d_in[8];
    float* out = (float*)d_out;

    // 512 vertical blocks first (long-pole work starts immediately),
    // then 16384 horizontal warp-scan blocks (fine-grained fillers).
    irnn_fused_kernel<<<VGRID + HGRID, TPB>>>(x,
                                              w_up, b_up, w_right, b_right,
                                              w_down, b_down, w_left, b_left,
                                              out);
}

// round 17
// speedup vs baseline: 1.2797x; 1.2797x over previous
#include <cuda_runtime.h>

// Spacial IRNN: 4 directional relu-scans over [B,C,H,W] = [4,64,256,256] fp32.
// out[dir][b][c][h][w], dir: 0=up, 1=right, 2=down, 3=left.
// h_0 = x_edge (raw), h_t = relu(w_c * h_{t-1} + b_c + x_t).
//
// Identity: maps h -> max(a*h + b, m) are closed under composition (a>=0):
//   outer(a,b,m) o inner(a1,b1,m1) = (a*a1, a*b1+b, max(a*m1+b, m)).
// Element map: h -> max(w*h + (b+x), 0); row edge element: (0, x_edge, -1e30).
//
// Horizontal: ONE WARP PER ROW, both directions from one register-resident
// load. Lane owns 8 contiguous elements: serial 8-map compose (registers),
// 5-level Kogge-Stone over lane triples (15 shfl/direction), exclusive
// carry, serial rescan, coalesced float4 streaming stores.
// Vertical: R9-proven scalar path (one direction per block).

#define HH 256
#define WW 256
#define BB 4
#define CC 64

constexpr int HW = HH * WW;
constexpr long long DIRSZ = (long long)BB * CC * HH * WW;  // 16,777,216

constexpr int TPB = 256;
// 512 vertical blocks + 8192 horizontal blocks (8 row-warps each) = 8704
constexpr int NBLK = 8704;                      // = 512 * 17

__global__ void __launch_bounds__(TPB)
irnn_fused_kernel(const float* __restrict__ x,
                  const float* __restrict__ w_up,    const float* __restrict__ b_up,
                  const float* __restrict__ w_right, const float* __restrict__ b_right,
                  const float* __restrict__ w_down,  const float* __restrict__ b_down,
                  const float* __restrict__ w_left,  const float* __restrict__ b_left,
                  float* __restrict__ out)
{
    const int bid = blockIdx.x;
    const int tid = threadIdx.x;
    const int grp = bid / 17;
    const int rem = bid % 17;

    if (rem == 0) {
        // ---------------- vertical: one direction, one thread per column ----
        const int isUp = grp & 1;            // 0 = down, 1 = up
        const int unit = grp >> 1;           // 0 .. 255

        const int id = unit * TPB + tid;     // 0 .. B*C*W-1
        const int w  = id & (WW - 1);
        const int bc = id >> 8;
        const int c  = bc & (CC - 1);

        const float* xp = x + (size_t)bc * HW + w;

        if (!isUp) {
            float* od = out + 2 * DIRSZ + (size_t)bc * HW + w;   // down
            const float wd = w_down[c], bd = b_down[c];
            float s = xp[0];
            __stcs(&od[0], s);
#pragma unroll 8
            for (int h = 1; h < HH; ++h) {
                float xv = xp[h * WW];
                s = fmaxf(fmaf(wd, s, bd + xv), 0.0f);
                __stcs(&od[h * WW], s);
            }
        } else {
            float* ou = out + 0 * DIRSZ + (size_t)bc * HW + w;   // up
            const float wu = w_up[c], bu = b_up[c];
            float s = xp[(HH - 1) * WW];
            __stcs(&ou[(HH - 1) * WW], s);
#pragma unroll 8
            for (int h = HH - 2; h >= 0; --h) {
                float xv = xp[h * WW];
                s = fmaxf(fmaf(wu, s, bu + xv), 0.0f);
                __stcs(&ou[h * WW], s);
            }
        }
    } else {
        // --------------- horizontal: one warp per row, both directions ------
        const int hrow = grp * 16 + (rem - 1);          // block-row group 0..8191
        const int wrp  = tid >> 5;                      // 0..7
        const int lane = tid & 31;
        const int row  = hrow * 8 + wrp;                // 0 .. 65535
        const int c    = (row >> 8) & (CC - 1);

        const float* xr = x + (size_t)row * WW;
        float* orr = out + 1 * DIRSZ + (size_t)row * WW;   // right
        float* oll = out + 3 * DIRSZ + (size_t)row * WW;   // left

        const float wr = w_right[c], br = b_right[c];
        const float wl = w_left[c],  bl = b_left[c];

        // lane owns elements [8*lane, 8*lane+8)
        float4 v0 = *(const float4*)&xr[lane * 8];
        float4 v1 = *(const float4*)&xr[lane * 8 + 4];
        float e[8] = {v0.x, v0.y, v0.z, v0.w, v1.x, v1.y, v1.z, v1.w};

        const unsigned FULL = 0xffffffffu;

        // =================== RIGHT (forward) ===================
        {
            // serial compose of this lane's 8 element maps (in order 0..7)
            float a, b, m;
            if (lane == 0) { a = 0.0f; b = e[0]; m = -1e30f; }      // edge
            else           { a = wr;   b = br + e[0]; m = 0.0f; }
#pragma unroll
            for (int i = 1; i < 8; ++i) {
                float bo = br + e[i];
                b = fmaf(wr, b, bo);
                m = fmaxf(fmaf(wr, m, bo), 0.0f);
                a = a * wr;
            }
            // inclusive Kogge-Stone (cur = outer, shfl'd = inner)
#pragma unroll
            for (int d = 1; d < 32; d <<= 1) {
                float a1 = __shfl_up_sync(FULL, a, d);
                float b1 = __shfl_up_sync(FULL, b, d);
                float m1 = __shfl_up_sync(FULL, m, d);
                if (lane >= d) {
                    m = fmaxf(fmaf(a, m1, b), m);
                    b = fmaf(a, b1, b);
                    a = a * a1;
                }
            }
            // exclusive carry: state entering this lane's segment
            float be = __shfl_up_sync(FULL, b, 1);
            float me = __shfl_up_sync(FULL, m, 1);
            float h  = (lane == 0) ? 0.0f : fmaxf(be, me);
            // serial rescan + store
            float o[8];
            if (lane == 0) h = e[0];
            else           h = fmaxf(fmaf(wr, h, br + e[0]), 0.0f);
            o[0] = h;
#pragma unroll
            for (int i = 1; i < 8; ++i) {
                h = fmaxf(fmaf(wr, h, br + e[i]), 0.0f);
                o[i] = h;
            }
            __stcs((float4*)&orr[lane * 8],     make_float4(o[0], o[1], o[2], o[3]));
            __stcs((float4*)&orr[lane * 8 + 4], make_float4(o[4], o[5], o[6], o[7]));
        }

        // =================== LEFT (backward) ===================
        {
            // processing order: element 7 down to 0; edge = lane31 elem 7
            float a, b, m;
            if (lane == 31) { a = 0.0f; b = e[7]; m = -1e30f; }     // edge
            else            { a = wl;   b = bl + e[7]; m = 0.0f; }
#pragma unroll
            for (int i = 6; i >= 0; --i) {
                float bo = bl + e[i];
                b = fmaf(wl, b, bo);
                m = fmaxf(fmaf(wl, m, bo), 0.0f);
                a = a * wl;
            }
            // inclusive Kogge-Stone toward lower lanes
#pragma unroll
            for (int d = 1; d < 32; d <<= 1) {
                float a1 = __shfl_down_sync(FULL, a, d);
                float b1 = __shfl_down_sync(FULL, b, d);
                float m1 = __shfl_down_sync(FULL, m, d);
                if (lane + d < 32) {
                    m = fmaxf(fmaf(a, m1, b), m);
                    b = fmaf(a, b1, b);
                    a = a * a1;
                }
            }
            float be = __shfl_down_sync(FULL, b, 1);
            float me = __shfl_down_sync(FULL, m, 1);
            float h  = (lane == 31) ? 0.0f : fmaxf(be, me);
            float o[8];
            if (lane == 31) h = e[7];
            else            h = fmaxf(fmaf(wl, h, bl + e[7]), 0.0f);
            o[7] = h;
#pragma unroll
            for (int i = 6; i >= 0; --i) {
                h = fmaxf(fmaf(wl, h, bl + e[i]), 0.0f);
                o[i] = h;
            }
            __stcs((float4*)&oll[lane * 8],     make_float4(o[0], o[1], o[2], o[3]));
            __stcs((float4*)&oll[lane * 8 + 4], make_float4(o[4], o[5], o[6], o[7]));
        }
    }
}

extern "C" void kernel_launch(void* const* d_in, const int* in_sizes, int n_in,
                              void* d_out, int out_size)
{
    const float* x       = (const float*)d_in[0];
    const float* w_up    = (const float*)d_in[1];
    const float* w_right = (const float*)d_in[2];
    const float* w_down  = (const float*)d_in[3];
    const float* w_left  = (const float*)d_in[4];
    const float* b_up    = (const float*)d_in[5];
    const float* b_right = (const float*)d_in[6];
    const float* b_down  = (const float*)d_in[7];
    const float* b_left  = (const float*)d_in[8];
    float* out = (float*)d_out;

    // 512 vertical + 8192 horizontal (8 row-warps each), 1:16 interleave.
    irnn_fused_kernel<<<NBLK, TPB>>>(x,
                                     w_up, b_up, w_right, b_right,
                                     w_down, b_down, w_left, b_left,
                                     out);
}